// round 8
// baseline (speedup 1.0000x reference)
#include <cuda_runtime.h>
#include <cstdint>

#define S_LEN   2048
#define D_K     64
#define BH      64
#define MT      128
#define NT      64
#define PADK    68   // (4x+tig) bank pattern -> conflict-free
#define PADV    72   // (8tig+g) bank pattern -> conflict-free
#define THREADS 256
#define NBLOCKS (BH * (S_LEN / MT))   // 1024

__device__ float g_linv[BH * S_LEN];
__device__ int   g_queue[NBLOCKS];
__device__ int   g_push;
__device__ int   g_ticket;

__device__ __forceinline__ uint32_t f2tf32(float x) {
    uint32_t r;
    asm("cvt.rna.tf32.f32 %0, %1;" : "=r"(r) : "f"(x));
    return r;
}

__device__ __forceinline__ void mma_tf32(float c[4],
                                         uint32_t a0, uint32_t a1, uint32_t a2, uint32_t a3,
                                         uint32_t b0, uint32_t b1) {
    asm volatile(
        "mma.sync.aligned.m16n8k8.row.col.f32.tf32.tf32.f32 "
        "{%0,%1,%2,%3},{%4,%5,%6,%7},{%8,%9},{%0,%1,%2,%3};"
        : "+f"(c[0]), "+f"(c[1]), "+f"(c[2]), "+f"(c[3])
        : "r"(a0), "r"(a1), "r"(a2), "r"(a3), "r"(b0), "r"(b1));
}

__device__ __forceinline__ void cp_async16(uint32_t s, const void* g) {
    asm volatile("cp.async.cg.shared.global [%0], [%1], 16;" :: "r"(s), "l"(g));
}
#define CP_COMMIT() asm volatile("cp.async.commit_group;")
#define CP_WAIT1()  asm volatile("cp.async.wait_group 1;")
#define CP_WAIT0()  asm volatile("cp.async.wait_group 0;")

// one 64x64 fp32 tile (K or V) -> padded smem
__device__ __forceinline__ void cp_tile(uint32_t dst_base, const float* __restrict__ src,
                                        int tid, int pad) {
    #pragma unroll
    for (int i = 0; i < 4; i++) {
        int idx = i * THREADS + tid;
        int row = idx >> 4;
        int c4  = (idx & 15) << 2;
        cp_async16(dst_base + (row * pad + c4) * 4, src + idx * 4);
    }
}

// Q tile 128x64: scale folded, tf32
__device__ __forceinline__ void load_q(float* Qs, const float* __restrict__ Qg, int tid) {
    const float4* q4 = (const float4*)Qg;
    #pragma unroll
    for (int i = 0; i < 8; i++) {
        int idx = i * THREADS + tid;          // 2048 float4
        float4 v = q4[idx];
        int row = idx >> 4;
        int c4  = (idx & 15) << 2;
        float* d = Qs + row * PADK + c4;
        d[0] = __uint_as_float(f2tf32(v.x * 0.125f));
        d[1] = __uint_as_float(f2tf32(v.y * 0.125f));
        d[2] = __uint_as_float(f2tf32(v.z * 0.125f));
        d[3] = __uint_as_float(f2tf32(v.w * 0.125f));
    }
}

__global__ __launch_bounds__(THREADS, 3)
void sdpa_fused(const float* __restrict__ Q, const float* __restrict__ K,
                const float* __restrict__ V, const int* __restrict__ mask,
                float* __restrict__ out) {
    extern __shared__ float sm[];
    float* Qs  = sm;                         // 128 x PADK
    float* Ks  = Qs + MT * PADK;             // 64 x PADK
    float* Vs  = Ks + NT * PADK;             // 64 x PADV
    float* Ps  = Vs + NT * PADV;             // 128 x PADK
    float* red = Ps + MT * PADK;             // 128 x 2
    float* liS = red + MT * 2;               // 128
    __shared__ int s_strip;

    const uint32_t base = (uint32_t)__cvta_generic_to_shared(sm);
    const uint32_t KsA = base + MT * PADK * 4;
    const uint32_t VsA = KsA + NT * PADK * 4;

    const int bh  = blockIdx.y;
    const int q0  = blockIdx.x * MT;
    const int myid = blockIdx.y * gridDim.x + blockIdx.x;
    const int tid = threadIdx.x;
    const int lane = tid & 31, wid = tid >> 5;
    const int g = lane >> 2, tig = lane & 3;
    const int wm = wid & 3;                  // 4 warps in M (32 rows each)
    const int wn = wid >> 2;                 // 2 warps in N (32 cols each)

    const float* Qg = Q + ((size_t)bh * S_LEN + q0) * D_K;
    const float* Kg = K + (size_t)bh * S_LEN * D_K;
    const float* Vg = V + (size_t)bh * S_LEN * D_K;
    const int*   Mg = mask + (size_t)bh * S_LEN * S_LEN;
    float* ctx  = out + (size_t)bh * S_LEN * D_K;
    float* attn_base = out + (size_t)BH * S_LEN * D_K;
    float* attn = attn_base + (size_t)bh * S_LEN * S_LEN;

    load_q(Qs, Qg, tid);
    cp_tile(KsA, Kg, tid, PADK);           // K(0)
    CP_COMMIT();

    float o[2][4][4] = {};                 // [mb][nf][..]
    float lp[2][2] = {};

    for (int kt = 0; kt < S_LEN; kt += NT) {
        CP_WAIT0();                        // K(t) arrived
        __syncthreads();                   // K visible; prev PV done (Vs free)

        cp_tile(VsA, Vg + (size_t)kt * D_K, tid, PADV);   // V(t)
        CP_COMMIT();

        // mask prefetch compressed to one bitmask (overlaps QK, saves 15 regs)
        uint32_t mbits = 0;
        #pragma unroll
        for (int mb = 0; mb < 2; mb++) {
            int row = wm * 32 + mb * 16 + g;
            #pragma unroll
            for (int nf = 0; nf < 4; nf++) {
                int col = wn * 32 + nf * 8 + 2 * tig;
                int2 m0 = *(const int2*)(Mg + (size_t)(q0 + row)     * S_LEN + kt + col);
                int2 m1 = *(const int2*)(Mg + (size_t)(q0 + row + 8) * S_LEN + kt + col);
                int b = (mb * 4 + nf) * 4;
                mbits |= ((m0.x ? 1u : 0u) << b) | ((m0.y ? 2u : 0u) << b)
                       | ((m1.x ? 4u : 0u) << b) | ((m1.y ? 8u : 0u) << b);
            }
        }

        // ---- S = Q K^T ----
        float acc[2][4][4] = {};
        #pragma unroll
        for (int j = 0; j < 8; j++) {
            int k0 = j * 8;
            uint32_t a[2][4];
            #pragma unroll
            for (int mb = 0; mb < 2; mb++) {
                int r0 = wm * 32 + mb * 16 + g;
                a[mb][0] = __float_as_uint(Qs[r0       * PADK + k0 + tig]);
                a[mb][1] = __float_as_uint(Qs[(r0 + 8) * PADK + k0 + tig]);
                a[mb][2] = __float_as_uint(Qs[r0       * PADK + k0 + tig + 4]);
                a[mb][3] = __float_as_uint(Qs[(r0 + 8) * PADK + k0 + tig + 4]);
            }
            #pragma unroll
            for (int nf = 0; nf < 4; nf++) {
                int nc = wn * 32 + nf * 8 + g;
                uint32_t b0 = f2tf32(Ks[nc * PADK + k0 + tig]);
                uint32_t b1 = f2tf32(Ks[nc * PADK + k0 + tig + 4]);
                #pragma unroll
                for (int mb = 0; mb < 2; mb++)
                    mma_tf32(acc[mb][nf], a[mb][0], a[mb][1], a[mb][2], a[mb][3], b0, b1);
            }
        }
        __syncthreads();                   // done reading Ks

        // prefetch K(t+1) (hidden behind exp/attn-write/PV)
        const float* Knext = (kt + NT < S_LEN) ? Kg + (size_t)(kt + NT) * D_K : Kg;
        cp_tile(KsA, Knext, tid, PADK);
        CP_COMMIT();

        // ---- p = mask*exp(s): write attn, stage P, sum rows ----
        #pragma unroll
        for (int mb = 0; mb < 2; mb++) {
            int row = wm * 32 + mb * 16 + g;
            #pragma unroll
            for (int nf = 0; nf < 4; nf++) {
                int col = wn * 32 + nf * 8 + 2 * tig;
                int b = (mb * 4 + nf) * 4;
                float p00 = (mbits >> b & 1u) ? __expf(acc[mb][nf][0]) : 0.f;
                float p01 = (mbits >> b & 2u) ? __expf(acc[mb][nf][1]) : 0.f;
                float p10 = (mbits >> b & 4u) ? __expf(acc[mb][nf][2]) : 0.f;
                float p11 = (mbits >> b & 8u) ? __expf(acc[mb][nf][3]) : 0.f;
                lp[mb][0] += p00 + p01;
                lp[mb][1] += p10 + p11;
                *(float2*)(attn + (size_t)(q0 + row)     * S_LEN + kt + col) = make_float2(p00, p01);
                *(float2*)(attn + (size_t)(q0 + row + 8) * S_LEN + kt + col) = make_float2(p10, p11);
                float2 s0, s1;
                s0.x = __uint_as_float(f2tf32(p00)); s0.y = __uint_as_float(f2tf32(p01));
                s1.x = __uint_as_float(f2tf32(p10)); s1.y = __uint_as_float(f2tf32(p11));
                *(float2*)&Ps[row       * PADK + col] = s0;
                *(float2*)&Ps[(row + 8) * PADK + col] = s1;
            }
        }

        CP_WAIT1();                        // V(t) done (K(t+1) in flight)
        __syncthreads();                   // Ps + Vs visible

        // ---- O += P V ----
        #pragma unroll
        for (int j = 0; j < 8; j++) {
            int kk = j * 8;
            uint32_t a[2][4];
            #pragma unroll
            for (int mb = 0; mb < 2; mb++) {
                int r0 = wm * 32 + mb * 16 + g;
                a[mb][0] = __float_as_uint(Ps[r0       * PADK + kk + tig]);
                a[mb][1] = __float_as_uint(Ps[(r0 + 8) * PADK + kk + tig]);
                a[mb][2] = __float_as_uint(Ps[r0       * PADK + kk + tig + 4]);
                a[mb][3] = __float_as_uint(Ps[(r0 + 8) * PADK + kk + tig + 4]);
            }
            #pragma unroll
            for (int nf = 0; nf < 4; nf++) {
                int dc = wn * 32 + nf * 8 + g;
                uint32_t b0 = f2tf32(Vs[(kk + tig)     * PADV + dc]);
                uint32_t b1 = f2tf32(Vs[(kk + tig + 4) * PADV + dc]);
                #pragma unroll
                for (int mb = 0; mb < 2; mb++)
                    mma_tf32(o[mb][nf], a[mb][0], a[mb][1], a[mb][2], a[mb][3], b0, b1);
            }
        }
    }

    // ---- row sums -> l_inv ----
    #pragma unroll
    for (int mb = 0; mb < 2; mb++)
        #pragma unroll
        for (int h = 0; h < 2; h++) {
            float s = lp[mb][h];
            s += __shfl_xor_sync(0xffffffffu, s, 1);
            s += __shfl_xor_sync(0xffffffffu, s, 2);
            lp[mb][h] = s;
        }
    if (tig == 0)
        #pragma unroll
        for (int mb = 0; mb < 2; mb++)
            #pragma unroll
            for (int h = 0; h < 2; h++)
                red[(wm * 32 + mb * 16 + g + h * 8) * 2 + wn] = lp[mb][h];
    __syncthreads();
    if (tid < MT) {
        float li = 1.f / (red[tid * 2] + red[tid * 2 + 1]);
        liS[tid] = li;
        g_linv[(size_t)bh * S_LEN + q0 + tid] = li;
    }
    __syncthreads();

    // ---- write context ----
    #pragma unroll
    for (int mb = 0; mb < 2; mb++) {
        int row = wm * 32 + mb * 16 + g;
        float li0 = liS[row], li1 = liS[row + 8];
        #pragma unroll
        for (int nf = 0; nf < 4; nf++) {
            int col = wn * 32 + nf * 8 + 2 * tig;
            *(float2*)(ctx + (size_t)(q0 + row)     * D_K + col) =
                make_float2(o[mb][nf][0] * li0, o[mb][nf][1] * li0);
            *(float2*)(ctx + (size_t)(q0 + row + 8) * D_K + col) =
                make_float2(o[mb][nf][2] * li1, o[mb][nf][3] * li1);
        }
    }

    // ---- produce/consume: normalize one already-produced strip ----
    __threadfence();
    __syncthreads();
    if (tid == 0) {
        int idx = atomicAdd(&g_push, 1);
        asm volatile("st.release.gpu.global.s32 [%0], %1;"
                     :: "l"(g_queue + idx), "r"(myid) : "memory");
        int t = atomicAdd(&g_ticket, 1);
        int s;
        while (true) {
            asm volatile("ld.acquire.gpu.global.s32 %0, [%1];"
                         : "=r"(s) : "l"(g_queue + t) : "memory");
            if (s >= 0) break;
            __nanosleep(64);
        }
        s_strip = s;
    }
    __syncthreads();

    const int sid  = s_strip;
    const int sbh  = sid >> 4;                 // 16 strips per bh
    const int sq0  = (sid & 15) * MT;
    float* sattn = attn_base + (size_t)sbh * S_LEN * S_LEN + (size_t)sq0 * S_LEN;
    if (tid < MT) liS[tid] = g_linv[(size_t)sbh * S_LEN + sq0 + tid];
    __syncthreads();

    #pragma unroll 4
    for (int i = tid; i < MT * (S_LEN / 4); i += THREADS) {
        float li = liS[i >> 9];
        float4* p = (float4*)sattn + i;
        float4 v = *p;
        v.x *= li; v.y *= li; v.z *= li; v.w *= li;
        *p = v;
    }
}

extern "C" void kernel_launch(void* const* d_in, const int* in_sizes, int n_in,
                              void* d_out, int out_size) {
    const float* Q    = (const float*)d_in[0];
    const float* K    = (const float*)d_in[1];
    const float* V    = (const float*)d_in[2];
    const int*   mask = (const int*)d_in[3];
    float* out = (float*)d_out;

    void* addr;
    cudaGetSymbolAddress(&addr, g_queue);
    cudaMemsetAsync(addr, 0xFF, sizeof(int) * NBLOCKS);
    cudaGetSymbolAddress(&addr, g_push);
    cudaMemsetAsync(addr, 0, sizeof(int));
    cudaGetSymbolAddress(&addr, g_ticket);
    cudaMemsetAsync(addr, 0, sizeof(int));

    const int smem = (MT * PADK + NT * PADK + NT * PADV + MT * PADK + MT * 2 + MT) * sizeof(float);
    cudaFuncSetAttribute(sdpa_fused, cudaFuncAttributeMaxDynamicSharedMemorySize, smem);

    dim3 grid(S_LEN / MT, BH);   // (16, 64)
    sdpa_fused<<<grid, THREADS, smem>>>(Q, K, V, mask, out);
}

// round 9
// speedup vs baseline: 1.0429x; 1.0429x over previous
#include <cuda_runtime.h>
#include <cuda_fp16.h>
#include <cstdint>

#define S_LEN   2048
#define D_K     64
#define BH      64
#define MT      128
#define NT      64
#define PADK    68    // fp32 rows: (4g+tig) conflict-free
#define PADV2   72    // half2 rows: (8tig+g) conflict-free
#define THREADS 256
#define NBLOCKS (BH * (S_LEN / MT))   // 1024

__device__ float g_linv[BH * S_LEN];
__device__ int   g_queue[NBLOCKS];
__device__ int   g_push;
__device__ int   g_ticket;

__device__ __forceinline__ uint32_t f2tf32(float x) {
    uint32_t r;
    asm("cvt.rna.tf32.f32 %0, %1;" : "=r"(r) : "f"(x));
    return r;
}

__device__ __forceinline__ uint32_t pack_h2(float lo, float hi) {
    half2 h = __floats2half2_rn(lo, hi);
    return *(uint32_t*)&h;
}

__device__ __forceinline__ void mma_tf32(float c[4],
                                         uint32_t a0, uint32_t a1, uint32_t a2, uint32_t a3,
                                         uint32_t b0, uint32_t b1) {
    asm volatile(
        "mma.sync.aligned.m16n8k8.row.col.f32.tf32.tf32.f32 "
        "{%0,%1,%2,%3},{%4,%5,%6,%7},{%8,%9},{%0,%1,%2,%3};"
        : "+f"(c[0]), "+f"(c[1]), "+f"(c[2]), "+f"(c[3])
        : "r"(a0), "r"(a1), "r"(a2), "r"(a3), "r"(b0), "r"(b1));
}

__device__ __forceinline__ void mma_f16(float c[4],
                                        uint32_t a0, uint32_t a1, uint32_t a2, uint32_t a3,
                                        uint32_t b0, uint32_t b1) {
    asm volatile(
        "mma.sync.aligned.m16n8k16.row.col.f32.f16.f16.f32 "
        "{%0,%1,%2,%3},{%4,%5,%6,%7},{%8,%9},{%0,%1,%2,%3};"
        : "+f"(c[0]), "+f"(c[1]), "+f"(c[2]), "+f"(c[3])
        : "r"(a0), "r"(a1), "r"(a2), "r"(a3), "r"(b0), "r"(b1));
}

__device__ __forceinline__ void cp_async16(uint32_t s, const void* g) {
    asm volatile("cp.async.cg.shared.global [%0], [%1], 16;" :: "r"(s), "l"(g));
}
#define CP_COMMIT() asm volatile("cp.async.commit_group;")
#define CP_WAIT0()  asm volatile("cp.async.wait_group 0;")

// 64x64 fp32 K tile -> padded smem
__device__ __forceinline__ void cp_tile(uint32_t dst_base, const float* __restrict__ src,
                                        int tid) {
    #pragma unroll
    for (int i = 0; i < 4; i++) {
        int idx = i * THREADS + tid;
        int row = idx >> 4;
        int c4  = (idx & 15) << 2;
        cp_async16(dst_base + (row * PADK + c4) * 4, src + idx * 4);
    }
}

// Q tile 128x64: scale folded, tf32
__device__ __forceinline__ void load_q(float* Qs, const float* __restrict__ Qg, int tid) {
    const float4* q4 = (const float4*)Qg;
    #pragma unroll
    for (int i = 0; i < 8; i++) {
        int idx = i * THREADS + tid;
        float4 v = q4[idx];
        int row = idx >> 4;
        int c4  = (idx & 15) << 2;
        float* d = Qs + row * PADK + c4;
        d[0] = __uint_as_float(f2tf32(v.x * 0.125f));
        d[1] = __uint_as_float(f2tf32(v.y * 0.125f));
        d[2] = __uint_as_float(f2tf32(v.z * 0.125f));
        d[3] = __uint_as_float(f2tf32(v.w * 0.125f));
    }
}

__global__ __launch_bounds__(THREADS, 3)
void sdpa_fused(const float* __restrict__ Q, const float* __restrict__ K,
                const float* __restrict__ V, const int* __restrict__ mask,
                float* __restrict__ out) {
    extern __shared__ float sm[];
    float* Qs  = sm;                          // 128 x PADK fp32
    float* Ks  = Qs + MT * PADK;              // 64 x PADK fp32
    half2* Vh  = (half2*)(Ks + NT * PADK);    // 32 x PADV2 half2 (k-pairs x d)
    float* liS = (float*)(Vh + 32 * PADV2);   // 128
    __shared__ int s_strip;

    const uint32_t base = (uint32_t)__cvta_generic_to_shared(sm);
    const uint32_t KsA = base + MT * PADK * 4;

    const int bh  = blockIdx.y;
    const int q0  = blockIdx.x * MT;
    const int myid = blockIdx.y * gridDim.x + blockIdx.x;
    const int tid = threadIdx.x;
    const int lane = tid & 31, wid = tid >> 5;
    const int g = lane >> 2, tig = lane & 3;
    const int r0 = wid * 16;                  // this warp's row band

    const float* Qg = Q + ((size_t)bh * S_LEN + q0) * D_K;
    const float* Kg = K + (size_t)bh * S_LEN * D_K;
    const float* Vg = V + (size_t)bh * S_LEN * D_K;
    const int*   Mg = mask + (size_t)bh * S_LEN * S_LEN;
    float* ctx  = out + (size_t)bh * S_LEN * D_K;
    float* attn_base = out + (size_t)BH * S_LEN * D_K;
    float* attn = attn_base + (size_t)bh * S_LEN * S_LEN;

    // V staging indices
    const int vk2l = tid >> 4;      // 0..15
    const int vdq  = tid & 15;      // d quad

    load_q(Qs, Qg, tid);
    cp_tile(KsA, Kg, tid);          // K(0)
    CP_COMMIT();

    float o[8][4] = {};             // rows (r0+g, r0+g+8) x d-cols (8nfd+2tig,+1)
    float lp[2] = {};               // unnormalized row sums (rows r0+g, r0+g+8)

    for (int kt = 0; kt < S_LEN; kt += NT) {
        CP_WAIT0();
        __syncthreads();            // K(t) visible; Vh free

        #pragma unroll
        for (int h = 0; h < 2; h++) {
            // ---- V half-h LDG (hidden behind QK) ----
            int vrow = kt + 32 * h + 2 * vk2l;
            float4 va = *((const float4*)(Vg + (size_t)vrow * D_K) + vdq);
            float4 vb = *((const float4*)(Vg + (size_t)(vrow + 1) * D_K) + vdq);

            // ---- mask prefetch (16 bits) ----
            uint32_t mbits = 0;
            #pragma unroll
            for (int nf = 0; nf < 4; nf++) {
                int col = 32 * h + nf * 8 + 2 * tig;
                int2 m0 = *(const int2*)(Mg + (size_t)(q0 + r0 + g)     * S_LEN + kt + col);
                int2 m1 = *(const int2*)(Mg + (size_t)(q0 + r0 + g + 8) * S_LEN + kt + col);
                int b = nf * 4;
                mbits |= ((m0.x ? 1u : 0u) << b) | ((m0.y ? 2u : 0u) << b)
                       | ((m1.x ? 4u : 0u) << b) | ((m1.y ? 8u : 0u) << b);
            }

            // ---- S(cols 32h..32h+31) = Q K^T ----
            float acc[4][4] = {};
            #pragma unroll
            for (int j = 0; j < 8; j++) {
                int k0 = j * 8;
                uint32_t a0 = __float_as_uint(Qs[(r0 + g)     * PADK + k0 + tig]);
                uint32_t a1 = __float_as_uint(Qs[(r0 + g + 8) * PADK + k0 + tig]);
                uint32_t a2 = __float_as_uint(Qs[(r0 + g)     * PADK + k0 + tig + 4]);
                uint32_t a3 = __float_as_uint(Qs[(r0 + g + 8) * PADK + k0 + tig + 4]);
                #pragma unroll
                for (int nf = 0; nf < 4; nf++) {
                    int nc = 32 * h + nf * 8 + g;
                    uint32_t b0 = f2tf32(Ks[nc * PADK + k0 + tig]);
                    uint32_t b1 = f2tf32(Ks[nc * PADK + k0 + tig + 4]);
                    mma_tf32(acc[nf], a0, a1, a2, a3, b0, b1);
                }
            }

            if (h == 1) {
                __syncthreads();    // all warps done reading Ks
                const float* Knext = (kt + NT < S_LEN) ? Kg + (size_t)(kt + NT) * D_K : Kg;
                cp_tile(KsA, Knext, tid);
                CP_COMMIT();
            }

            // ---- V half-h convert + STS (half2 k-pairs) ----
            {
                uint32_t h0 = pack_h2(va.x, vb.x);
                uint32_t h1 = pack_h2(va.y, vb.y);
                uint32_t h2v = pack_h2(va.z, vb.z);
                uint32_t h3 = pack_h2(va.w, vb.w);
                uint32_t* dst = (uint32_t*)(Vh + (16 * h + vk2l) * PADV2 + 4 * vdq);
                *(uint4*)dst = make_uint4(h0, h1, h2v, h3);
            }

            // ---- p = mask*exp(s): attn write, pack fp16 A frags, row sums ----
            uint32_t pa[2][4];
            #pragma unroll
            for (int nf = 0; nf < 4; nf++) {
                int col = 32 * h + nf * 8 + 2 * tig;
                int b = nf * 4;
                float p00 = (mbits >> b & 1u) ? __expf(acc[nf][0]) : 0.f;
                float p01 = (mbits >> b & 2u) ? __expf(acc[nf][1]) : 0.f;
                float p10 = (mbits >> b & 4u) ? __expf(acc[nf][2]) : 0.f;
                float p11 = (mbits >> b & 8u) ? __expf(acc[nf][3]) : 0.f;
                lp[0] += p00 + p01;
                lp[1] += p10 + p11;
                *(float2*)(attn + (size_t)(q0 + r0 + g)     * S_LEN + kt + col) = make_float2(p00, p01);
                *(float2*)(attn + (size_t)(q0 + r0 + g + 8) * S_LEN + kt + col) = make_float2(p10, p11);
                int c = nf >> 1, e = (nf & 1) * 2;
                pa[c][e]     = pack_h2(p00, p01);
                pa[c][e + 1] = pack_h2(p10, p11);
            }

            __syncthreads();        // Vh half-h visible to all warps

            // ---- O += P(k half-h) V : fp16 mma, A from registers ----
            #pragma unroll
            for (int c = 0; c < 2; c++) {
                int k2b = 16 * h + 8 * c;
                #pragma unroll
                for (int nfd = 0; nfd < 8; nfd++) {
                    uint32_t b0 = *(uint32_t*)&Vh[(k2b + tig)     * PADV2 + 8 * nfd + g];
                    uint32_t b1 = *(uint32_t*)&Vh[(k2b + tig + 4) * PADV2 + 8 * nfd + g];
                    mma_f16(o[nfd], pa[c][0], pa[c][1], pa[c][2], pa[c][3], b0, b1);
                }
            }
        }
    }

    // ---- row sums -> l_inv (quad reduction; each row owned by one warp) ----
    #pragma unroll
    for (int hh = 0; hh < 2; hh++) {
        float s = lp[hh];
        s += __shfl_xor_sync(0xffffffffu, s, 1);
        s += __shfl_xor_sync(0xffffffffu, s, 2);
        lp[hh] = s;
    }
    float li0 = 1.f / lp[0], li1 = 1.f / lp[1];
    if (tig == 0) {
        g_linv[(size_t)bh * S_LEN + q0 + r0 + g]     = li0;
        g_linv[(size_t)bh * S_LEN + q0 + r0 + g + 8] = li1;
    }

    // ---- write context ----
    #pragma unroll
    for (int nfd = 0; nfd < 8; nfd++) {
        int col = 8 * nfd + 2 * tig;
        *(float2*)(ctx + (size_t)(q0 + r0 + g)     * D_K + col) =
            make_float2(o[nfd][0] * li0, o[nfd][1] * li0);
        *(float2*)(ctx + (size_t)(q0 + r0 + g + 8) * D_K + col) =
            make_float2(o[nfd][2] * li1, o[nfd][3] * li1);
    }

    // ---- produce/consume: normalize one already-produced strip ----
    __threadfence();
    __syncthreads();
    if (tid == 0) {
        int idx = atomicAdd(&g_push, 1);
        asm volatile("st.release.gpu.global.s32 [%0], %1;"
                     :: "l"(g_queue + idx), "r"(myid) : "memory");
        int t = atomicAdd(&g_ticket, 1);
        int s;
        while (true) {
            asm volatile("ld.acquire.gpu.global.s32 %0, [%1];"
                         : "=r"(s) : "l"(g_queue + t) : "memory");
            if (s >= 0) break;
            __nanosleep(64);
        }
        s_strip = s;
    }
    __syncthreads();

    const int sid  = s_strip;
    const int sbh  = sid >> 4;                 // 16 strips per bh
    const int sq0  = (sid & 15) * MT;
    float* sattn = attn_base + (size_t)sbh * S_LEN * S_LEN + (size_t)sq0 * S_LEN;
    if (tid < MT) liS[tid] = g_linv[(size_t)sbh * S_LEN + sq0 + tid];
    __syncthreads();

    #pragma unroll 4
    for (int i = tid; i < MT * (S_LEN / 4); i += THREADS) {
        float li = liS[i >> 9];
        float4* p = (float4*)sattn + i;
        float4 v = *p;
        v.x *= li; v.y *= li; v.z *= li; v.w *= li;
        *p = v;
    }
}

extern "C" void kernel_launch(void* const* d_in, const int* in_sizes, int n_in,
                              void* d_out, int out_size) {
    const float* Q    = (const float*)d_in[0];
    const float* K    = (const float*)d_in[1];
    const float* V    = (const float*)d_in[2];
    const int*   mask = (const int*)d_in[3];
    float* out = (float*)d_out;

    void* addr;
    cudaGetSymbolAddress(&addr, g_queue);
    cudaMemsetAsync(addr, 0xFF, sizeof(int) * NBLOCKS);
    cudaGetSymbolAddress(&addr, g_push);
    cudaMemsetAsync(addr, 0, sizeof(int));
    cudaGetSymbolAddress(&addr, g_ticket);
    cudaMemsetAsync(addr, 0, sizeof(int));

    // Qs + Ks fp32, Vh half2 (counts as PADV2*32 floats), liS
    const int smem = (MT * PADK + NT * PADK + 32 * PADV2 + MT) * sizeof(float);  // ~61 KB
    cudaFuncSetAttribute(sdpa_fused, cudaFuncAttributeMaxDynamicSharedMemorySize, smem);

    dim3 grid(S_LEN / MT, BH);   // (16, 64)
    sdpa_fused<<<grid, THREADS, smem>>>(Q, K, V, mask, out);
}

// round 10
// speedup vs baseline: 1.2385x; 1.1875x over previous
#include <cuda_runtime.h>
#include <cuda_fp16.h>
#include <cstdint>

#define S_LEN   2048
#define D_K     64
#define BH      64
#define MT      64
#define NT      64
#define PQ2     36    // half2 pad: Qh/Ph reads banks 4g+tig -> conflict-free
#define PKV2    72    // half2 pad: Kt/Vt reads banks 8tig+g -> conflict-free
#define THREADS 256
#define NBLOCKS (BH * (S_LEN / MT))   // 2048

__device__ float g_linv[BH * S_LEN];
__device__ int   g_queue[NBLOCKS];
__device__ int   g_push;
__device__ int   g_ticket;

__device__ __forceinline__ uint32_t pack_h2(float lo, float hi) {
    half2 h = __floats2half2_rn(lo, hi);
    return *(uint32_t*)&h;
}

__device__ __forceinline__ void mma_f16(float c[4],
                                        uint32_t a0, uint32_t a1, uint32_t a2, uint32_t a3,
                                        uint32_t b0, uint32_t b1) {
    asm volatile(
        "mma.sync.aligned.m16n8k16.row.col.f32.f16.f16.f32 "
        "{%0,%1,%2,%3},{%4,%5,%6,%7},{%8,%9},{%0,%1,%2,%3};"
        : "+f"(c[0]), "+f"(c[1]), "+f"(c[2]), "+f"(c[3])
        : "r"(a0), "r"(a1), "r"(a2), "r"(a3), "r"(b0), "r"(b1));
}

__global__ __launch_bounds__(THREADS, 3)
void sdpa_fused(const float* __restrict__ Q, const float* __restrict__ K,
                const float* __restrict__ V, const int* __restrict__ mask,
                float* __restrict__ out) {
    extern __shared__ char smraw[];
    half2* Qh = (half2*)smraw;               // 64 x PQ2  (row, k2)
    half2* Ph = Qh + MT * PQ2;               // 64 x PQ2  (row, k2)
    half2* Kt = Ph + MT * PQ2;               // 32 x PKV2 (k2, key)
    half2* Vt = Kt + 32 * PKV2;              // 32 x PKV2 (k2, d)
    float* red = (float*)(Vt + 32 * PKV2);   // 64 x 4
    float* liS = red + MT * 4;               // 64
    __shared__ int s_strip;

    const int bh  = blockIdx.y;
    const int q0  = blockIdx.x * MT;
    const int myid = blockIdx.y * gridDim.x + blockIdx.x;
    const int tid = threadIdx.x;
    const int lane = tid & 31, wid = tid >> 5;
    const int g = lane >> 2, tig = lane & 3;
    const int wm = wid & 1;                  // 2 warps in M (32 rows each)
    const int wn = wid >> 1;                 // 4 warps in N (16 cols each)

    const float* Qg = Q + ((size_t)bh * S_LEN + q0) * D_K;
    const float* Kg = K + (size_t)bh * S_LEN * D_K;
    const float* Vg = V + (size_t)bh * S_LEN * D_K;
    const int*   Mg = mask + (size_t)bh * S_LEN * S_LEN;
    float* ctx  = out + (size_t)bh * S_LEN * D_K;
    float* attn_base = out + (size_t)BH * S_LEN * D_K;
    float* attn = attn_base + (size_t)bh * S_LEN * S_LEN;

    // ---- Q -> fp16 smem (scale 1/8 folded) ----
    {
        const float4* q4 = (const float4*)Qg;
        #pragma unroll
        for (int i = 0; i < 4; i++) {
            int idx = i * THREADS + tid;
            float4 v = q4[idx];
            int row = idx >> 4;
            int c2  = (idx & 15) * 2;
            Qh[row * PQ2 + c2]     = __floats2half2_rn(v.x * 0.125f, v.y * 0.125f);
            Qh[row * PQ2 + c2 + 1] = __floats2half2_rn(v.z * 0.125f, v.w * 0.125f);
        }
    }

    // ---- preload K(0) into registers ----
    float4 kreg[4];
    #pragma unroll
    for (int i = 0; i < 4; i++) {
        int f = i * THREADS + tid;
        int key = f & 63, kb = f >> 6;
        kreg[i] = *(const float4*)(Kg + (size_t)key * D_K + kb * 4);
    }

    float o[2][2][4] = {};
    float lp[2][2] = {};

    for (int kt = 0; kt < S_LEN; kt += NT) {
        __syncthreads();                     // prev tile's smem consumers done

        // ---- K(t) STS from kreg (k2-major half2) ----
        #pragma unroll
        for (int i = 0; i < 4; i++) {
            int f = i * THREADS + tid;
            int key = f & 63, kb = f >> 6;
            Kt[(2 * kb)     * PKV2 + key] = __floats2half2_rn(kreg[i].x, kreg[i].y);
            Kt[(2 * kb + 1) * PKV2 + key] = __floats2half2_rn(kreg[i].z, kreg[i].w);
        }

        // ---- V(t) LDG (consumed after exp; long cover) ----
        float4 va[2], vb[2];
        {
            int dq = tid & 15;
            #pragma unroll
            for (int i2 = 0; i2 < 2; i2++) {
                int k2 = (tid >> 4) + 16 * i2;
                va[i2] = *(const float4*)(Vg + (size_t)(kt + 2 * k2)     * D_K + 4 * dq);
                vb[i2] = *(const float4*)(Vg + (size_t)(kt + 2 * k2 + 1) * D_K + 4 * dq);
            }
        }

        // ---- mask prefetch -> bitmask (overlaps QK) ----
        uint32_t mbits = 0;
        #pragma unroll
        for (int mb = 0; mb < 2; mb++) {
            int row = wm * 32 + mb * 16 + g;
            #pragma unroll
            for (int nf = 0; nf < 2; nf++) {
                int col = wn * 16 + nf * 8 + 2 * tig;
                int2 m0 = *(const int2*)(Mg + (size_t)(q0 + row)     * S_LEN + kt + col);
                int2 m1 = *(const int2*)(Mg + (size_t)(q0 + row + 8) * S_LEN + kt + col);
                int b = (mb * 2 + nf) * 4;
                mbits |= ((m0.x ? 1u : 0u) << b) | ((m0.y ? 2u : 0u) << b)
                       | ((m1.x ? 4u : 0u) << b) | ((m1.y ? 8u : 0u) << b);
            }
        }
        __syncthreads();                     // Kt visible

        // ---- S = Q K^T (fp16 mma, k16) ----
        float acc[2][2][4] = {};
        #pragma unroll
        for (int j = 0; j < 4; j++) {
            uint32_t a[2][4];
            #pragma unroll
            for (int mb = 0; mb < 2; mb++) {
                int r = wm * 32 + mb * 16 + g;
                a[mb][0] = *(uint32_t*)&Qh[r       * PQ2 + 8 * j + tig];
                a[mb][1] = *(uint32_t*)&Qh[(r + 8) * PQ2 + 8 * j + tig];
                a[mb][2] = *(uint32_t*)&Qh[r       * PQ2 + 8 * j + tig + 4];
                a[mb][3] = *(uint32_t*)&Qh[(r + 8) * PQ2 + 8 * j + tig + 4];
            }
            #pragma unroll
            for (int nf = 0; nf < 2; nf++) {
                int nc = wn * 16 + nf * 8 + g;
                uint32_t b0 = *(uint32_t*)&Kt[(8 * j + tig)     * PKV2 + nc];
                uint32_t b1 = *(uint32_t*)&Kt[(8 * j + tig + 4) * PKV2 + nc];
                #pragma unroll
                for (int mb = 0; mb < 2; mb++)
                    mma_f16(acc[mb][nf], a[mb][0], a[mb][1], a[mb][2], a[mb][3], b0, b1);
            }
        }

        // ---- p = mask*exp(s): attn write (fp32), Ph store (fp16), row sums ----
        #pragma unroll
        for (int mb = 0; mb < 2; mb++) {
            int row = wm * 32 + mb * 16 + g;
            #pragma unroll
            for (int nf = 0; nf < 2; nf++) {
                int col = wn * 16 + nf * 8 + 2 * tig;
                int b = (mb * 2 + nf) * 4;
                float p00 = (mbits >> b & 1u) ? __expf(acc[mb][nf][0]) : 0.f;
                float p01 = (mbits >> b & 2u) ? __expf(acc[mb][nf][1]) : 0.f;
                float p10 = (mbits >> b & 4u) ? __expf(acc[mb][nf][2]) : 0.f;
                float p11 = (mbits >> b & 8u) ? __expf(acc[mb][nf][3]) : 0.f;
                lp[mb][0] += p00 + p01;
                lp[mb][1] += p10 + p11;
                *(float2*)(attn + (size_t)(q0 + row)     * S_LEN + kt + col) = make_float2(p00, p01);
                *(float2*)(attn + (size_t)(q0 + row + 8) * S_LEN + kt + col) = make_float2(p10, p11);
                int k2i = wn * 8 + 4 * nf + tig;
                Ph[row       * PQ2 + k2i] = __floats2half2_rn(p00, p01);
                Ph[(row + 8) * PQ2 + k2i] = __floats2half2_rn(p10, p11);
            }
        }

        // ---- V(t) STS (k2-major half2) ----
        {
            int dq = tid & 15;
            #pragma unroll
            for (int i2 = 0; i2 < 2; i2++) {
                int k2 = (tid >> 4) + 16 * i2;
                uint4 h;
                h.x = pack_h2(va[i2].x, vb[i2].x);
                h.y = pack_h2(va[i2].y, vb[i2].y);
                h.z = pack_h2(va[i2].z, vb[i2].z);
                h.w = pack_h2(va[i2].w, vb[i2].w);
                *(uint4*)&Vt[k2 * PKV2 + 4 * dq] = h;
            }
        }

        // ---- K(t+1) LDG (vreg dead; cover = PV phase + next-tile start) ----
        {
            const float* Kn = Kg + (size_t)((kt + NT < S_LEN) ? kt + NT : 0) * D_K;
            #pragma unroll
            for (int i = 0; i < 4; i++) {
                int f = i * THREADS + tid;
                int key = f & 63, kb = f >> 6;
                kreg[i] = *(const float4*)(Kn + (size_t)key * D_K + kb * 4);
            }
        }
        __syncthreads();                     // Ph + Vt visible

        // ---- O += P V (fp16 mma, k16) ----
        #pragma unroll
        for (int j = 0; j < 4; j++) {
            uint32_t a[2][4];
            #pragma unroll
            for (int mb = 0; mb < 2; mb++) {
                int r = wm * 32 + mb * 16 + g;
                a[mb][0] = *(uint32_t*)&Ph[r       * PQ2 + 8 * j + tig];
                a[mb][1] = *(uint32_t*)&Ph[(r + 8) * PQ2 + 8 * j + tig];
                a[mb][2] = *(uint32_t*)&Ph[r       * PQ2 + 8 * j + tig + 4];
                a[mb][3] = *(uint32_t*)&Ph[(r + 8) * PQ2 + 8 * j + tig + 4];
            }
            #pragma unroll
            for (int nf = 0; nf < 2; nf++) {
                int dc = wn * 16 + nf * 8 + g;
                uint32_t b0 = *(uint32_t*)&Vt[(8 * j + tig)     * PKV2 + dc];
                uint32_t b1 = *(uint32_t*)&Vt[(8 * j + tig + 4) * PKV2 + dc];
                #pragma unroll
                for (int mb = 0; mb < 2; mb++)
                    mma_f16(o[mb][nf], a[mb][0], a[mb][1], a[mb][2], a[mb][3], b0, b1);
            }
        }
    }

    // ---- row sums -> l_inv ----
    #pragma unroll
    for (int mb = 0; mb < 2; mb++)
        #pragma unroll
        for (int h = 0; h < 2; h++) {
            float s = lp[mb][h];
            s += __shfl_xor_sync(0xffffffffu, s, 1);
            s += __shfl_xor_sync(0xffffffffu, s, 2);
            lp[mb][h] = s;
        }
    if (tig == 0)
        #pragma unroll
        for (int mb = 0; mb < 2; mb++)
            #pragma unroll
            for (int h = 0; h < 2; h++)
                red[(wm * 32 + mb * 16 + g + h * 8) * 4 + wn] = lp[mb][h];
    __syncthreads();
    if (tid < MT) {
        float li = 1.f / (red[tid * 4] + red[tid * 4 + 1] + red[tid * 4 + 2] + red[tid * 4 + 3]);
        liS[tid] = li;
        g_linv[(size_t)bh * S_LEN + q0 + tid] = li;
    }
    __syncthreads();

    // ---- write context ----
    #pragma unroll
    for (int mb = 0; mb < 2; mb++) {
        int row = wm * 32 + mb * 16 + g;
        float li0 = liS[row], li1 = liS[row + 8];
        #pragma unroll
        for (int nf = 0; nf < 2; nf++) {
            int col = wn * 16 + nf * 8 + 2 * tig;
            *(float2*)(ctx + (size_t)(q0 + row)     * D_K + col) =
                make_float2(o[mb][nf][0] * li0, o[mb][nf][1] * li0);
            *(float2*)(ctx + (size_t)(q0 + row + 8) * D_K + col) =
                make_float2(o[mb][nf][2] * li1, o[mb][nf][3] * li1);
        }
    }

    // ---- produce/consume: normalize one already-produced strip ----
    __threadfence();
    __syncthreads();
    if (tid == 0) {
        int idx = atomicAdd(&g_push, 1);
        asm volatile("st.release.gpu.global.s32 [%0], %1;"
                     :: "l"(g_queue + idx), "r"(myid) : "memory");
        int t = atomicAdd(&g_ticket, 1);
        int s;
        while (true) {
            asm volatile("ld.acquire.gpu.global.s32 %0, [%1];"
                         : "=r"(s) : "l"(g_queue + t) : "memory");
            if (s >= 0) break;
            __nanosleep(64);
        }
        s_strip = s;
    }
    __syncthreads();

    const int sid  = s_strip;
    const int sbh  = sid >> 5;
    const int sq0  = (sid & 31) * MT;
    float* sattn = attn_base + (size_t)sbh * S_LEN * S_LEN + (size_t)sq0 * S_LEN;
    if (tid < MT) liS[tid] = g_linv[(size_t)sbh * S_LEN + sq0 + tid];
    __syncthreads();

    #pragma unroll 4
    for (int i = tid; i < MT * (S_LEN / 4); i += THREADS) {
        float li = liS[i >> 9];
        float4* p = (float4*)sattn + i;
        float4 v = *p;
        v.x *= li; v.y *= li; v.z *= li; v.w *= li;
        *p = v;
    }
}

extern "C" void kernel_launch(void* const* d_in, const int* in_sizes, int n_in,
                              void* d_out, int out_size) {
    const float* Q    = (const float*)d_in[0];
    const float* K    = (const float*)d_in[1];
    const float* V    = (const float*)d_in[2];
    const int*   mask = (const int*)d_in[3];
    float* out = (float*)d_out;

    void* addr;
    cudaGetSymbolAddress(&addr, g_queue);
    cudaMemsetAsync(addr, 0xFF, sizeof(int) * NBLOCKS);
    cudaGetSymbolAddress(&addr, g_push);
    cudaMemsetAsync(addr, 0, sizeof(int));
    cudaGetSymbolAddress(&addr, g_ticket);
    cudaMemsetAsync(addr, 0, sizeof(int));

    const int smem = (2 * MT * PQ2 + 2 * 32 * PKV2) * 4 + (MT * 4 + MT) * sizeof(float);  // ~38 KB
    cudaFuncSetAttribute(sdpa_fused, cudaFuncAttributeMaxDynamicSharedMemorySize, smem);

    dim3 grid(S_LEN / MT, BH);   // (32, 64)
    sdpa_fused<<<grid, THREADS, smem>>>(Q, K, V, mask, out);
}